// round 1
// baseline (speedup 1.0000x reference)
#include <cuda_runtime.h>
#include <cuda_bf16.h>
#include <math.h>

#define BATCH 2
#define NPTS 4096
#define DM 512
#define NH 8
#define DH 64
#define KNB 16
#define ROWS (BATCH * NPTS)   // 8192

// ---------------- scratch (device globals; no allocation allowed) ----------------
__device__ float g_Q[ROWS * DM];
__device__ float g_K[ROWS * DM];
__device__ float g_V[ROWS * DM];
__device__ float g_att[ROWS * DM];
__device__ float g_tmp[ROWS * DM];
__device__ int   g_idx[ROWS * KNB];

// ---------------- kNN: brute force, thread per query, top-17 insertion list ------
__global__ void knn_kernel(const float* __restrict__ pos) {
    int q = blockIdx.x * blockDim.x + threadIdx.x;   // 0..8191
    int b = q >> 12;
    int n = q & (NPTS - 1);
    const float* pb = pos + (size_t)b * NPTS * 3;
    float qx = pb[n * 3 + 0], qy = pb[n * 3 + 1], qz = pb[n * 3 + 2];

    float dist[KNB + 1];
    int   didx[KNB + 1];
#pragma unroll
    for (int i = 0; i < KNB + 1; i++) { dist[i] = INFINITY; didx[i] = 0x7fffffff; }
    float worstD = INFINITY; int worstI = 0x7fffffff;

    __shared__ float sp[128 * 3];
    for (int tile = 0; tile < NPTS; tile += 128) {
        __syncthreads();
        for (int t = threadIdx.x; t < 128 * 3; t += blockDim.x)
            sp[t] = pb[tile * 3 + t];
        __syncthreads();
        for (int j = 0; j < 128; j++) {
            float dx = qx - sp[j * 3 + 0];
            float dy = qy - sp[j * 3 + 1];
            float dz = qz - sp[j * 3 + 2];
            float d = fmaf(dx, dx, fmaf(dy, dy, dz * dz));
            int jj = tile + j;
            // top_k tie-break: smaller distance first, then smaller index
            bool better = (d < worstD) || (d == worstD && jj < worstI);
            if (better) {
                int p = KNB;
                while (p > 0 && (dist[p - 1] > d ||
                                 (dist[p - 1] == d && didx[p - 1] > jj))) {
                    dist[p] = dist[p - 1]; didx[p] = didx[p - 1]; p--;
                }
                dist[p] = d; didx[p] = jj;
                worstD = dist[KNB]; worstI = didx[KNB];
            }
        }
    }
    // drop slot 0 (self, distance exactly 0)
#pragma unroll
    for (int i = 0; i < KNB; i++)
        g_idx[q * KNB + i] = didx[i + 1];
}

// ---------------- SGEMM: C(MxN) = A(MxK) * B(KxN), all row-major, fp32 -----------
#define BM 128
#define BN 128
#define BKK 16
__global__ __launch_bounds__(256) void gemm_kernel(const float* __restrict__ A,
                                                   const float* __restrict__ B,
                                                   float* __restrict__ C,
                                                   int M, int N, int K) {
    __shared__ float As[BKK][BM];
    __shared__ float Bs[BKK][BN];
    int tid = threadIdx.x;             // 256
    int tx = tid & 15, ty = tid >> 4;  // 16 x 16
    int bm = blockIdx.y * BM, bn = blockIdx.x * BN;

    float acc[8][8];
#pragma unroll
    for (int i = 0; i < 8; i++)
#pragma unroll
        for (int j = 0; j < 8; j++) acc[i][j] = 0.0f;

    for (int k0 = 0; k0 < K; k0 += BKK) {
#pragma unroll
        for (int i = 0; i < 2; i++) {
            int v = i * 256 + tid;
            // A tile: 128 rows x 16 cols = 512 float4
            int r  = v >> 2;
            int c4 = (v & 3) << 2;
            float4 a = *(const float4*)&A[(size_t)(bm + r) * K + k0 + c4];
            As[c4 + 0][r] = a.x;
            As[c4 + 1][r] = a.y;
            As[c4 + 2][r] = a.z;
            As[c4 + 3][r] = a.w;
            // B tile: 16 rows x 128 cols = 512 float4
            int rb  = v >> 5;
            int cb4 = (v & 31) << 2;
            *(float4*)&Bs[rb][cb4] = *(const float4*)&B[(size_t)(k0 + rb) * N + bn + cb4];
        }
        __syncthreads();
#pragma unroll
        for (int kk = 0; kk < BKK; kk++) {
            float a[8], bf[8];
            *(float4*)&a[0]  = *(const float4*)&As[kk][ty * 8 + 0];
            *(float4*)&a[4]  = *(const float4*)&As[kk][ty * 8 + 4];
            *(float4*)&bf[0] = *(const float4*)&Bs[kk][tx * 8 + 0];
            *(float4*)&bf[4] = *(const float4*)&Bs[kk][tx * 8 + 4];
#pragma unroll
            for (int i = 0; i < 8; i++)
#pragma unroll
                for (int j = 0; j < 8; j++)
                    acc[i][j] = fmaf(a[i], bf[j], acc[i][j]);
        }
        __syncthreads();
    }
#pragma unroll
    for (int i = 0; i < 8; i++) {
        int r = bm + ty * 8 + i;
#pragma unroll
        for (int j = 0; j < 8; j += 4) {
            float4 o = make_float4(acc[i][j], acc[i][j + 1], acc[i][j + 2], acc[i][j + 3]);
            *(float4*)&C[(size_t)r * N + bn + tx * 8 + j] = o;
        }
    }
}

// ---------------- attention: one block per (b, n), 512 threads -------------------
__global__ __launch_bounds__(512) void attn_kernel(const int* __restrict__ nbr_unused,
                                                   const float* __restrict__ pos,
                                                   const float* __restrict__ Wpos,
                                                   const float* __restrict__ bpos,
                                                   const float* __restrict__ temp) {
    int row = blockIdx.x;          // b*4096 + n
    int b = row >> 12;
    int n = row & (NPTS - 1);
    int tid = threadIdx.x;         // 0..511
    int dd = tid & (DH - 1);       // dim within head
    int h  = tid >> 6;
    int warp = tid >> 5, lane = tid & 31;

    __shared__ float sv[KNB][DM];     // 32 KB: gathered V rows
    __shared__ float spart[KNB][16];  // per-warp score partials
    __shared__ float sw[NH][KNB];     // softmax weights

    float invT = 1.0f / temp[0];
    float qv = g_Q[(size_t)row * DM + tid] * invT;
    // pe uses only Wpos[:, :64] and bpos[:64]  (tile(...,4)[..., :64])
    float w0 = Wpos[0 * 128 + dd];
    float w1 = Wpos[1 * 128 + dd];
    float w2 = Wpos[2 * 128 + dd];
    float bp = bpos[dd];
    const float* posb = pos + (size_t)b * NPTS * 3;
    float px = posb[n * 3 + 0], py = posb[n * 3 + 1], pz = posb[n * 3 + 2];

#pragma unroll
    for (int k = 0; k < KNB; k++) {
        int j = g_idx[row * KNB + k];
        int kv = (b << 12) + j;
        float kval = g_K[(size_t)kv * DM + tid];
        float rx = px - posb[j * 3 + 0];
        float ry = py - posb[j * 3 + 1];
        float rz = pz - posb[j * 3 + 2];
        float pe = fmaf(rx, w0, fmaf(ry, w1, fmaf(rz, w2, bp)));
        float prod = qv * (kval + pe);
#pragma unroll
        for (int off = 16; off; off >>= 1)
            prod += __shfl_down_sync(0xffffffffu, prod, off);
        if (lane == 0) spart[k][warp] = prod;
        sv[k][tid] = g_V[(size_t)kv * DM + tid];
    }
    __syncthreads();

    if (tid < NH) {  // one thread per head does the softmax
        float s[KNB];
        float m = -INFINITY;
#pragma unroll
        for (int k = 0; k < KNB; k++) {
            s[k] = spart[k][2 * tid] + spart[k][2 * tid + 1];
            m = fmaxf(m, s[k]);
        }
        float sum = 0.0f;
#pragma unroll
        for (int k = 0; k < KNB; k++) { s[k] = __expf(s[k] - m); sum += s[k]; }
        float inv = 1.0f / sum;
#pragma unroll
        for (int k = 0; k < KNB; k++) sw[tid][k] = s[k] * inv;
    }
    __syncthreads();

    float acc = 0.0f;
#pragma unroll
    for (int k = 0; k < KNB; k++)
        acc = fmaf(sw[h][k], sv[k][tid], acc);
    g_att[(size_t)row * DM + tid] = acc;
}

// ---------------- epilogue: +bo, +residual, LayerNorm ----------------------------
__global__ __launch_bounds__(512) void ln_kernel(const float* __restrict__ feat,
                                                 const float* __restrict__ bo,
                                                 const float* __restrict__ gamma,
                                                 const float* __restrict__ beta,
                                                 float* __restrict__ out) {
    int row = blockIdx.x;
    int tid = threadIdx.x;  // 512
    int lane = tid & 31, warp = tid >> 5;
    __shared__ float red[16];
    __shared__ float mu_s, rs_s;

    float x = g_tmp[(size_t)row * DM + tid] + bo[tid] + feat[(size_t)row * DM + tid];

    float s = x;
#pragma unroll
    for (int o = 16; o; o >>= 1) s += __shfl_down_sync(0xffffffffu, s, o);
    if (!lane) red[warp] = s;
    __syncthreads();
    if (tid == 0) {
        float t = 0.0f;
#pragma unroll
        for (int i = 0; i < 16; i++) t += red[i];
        mu_s = t * (1.0f / DM);
    }
    __syncthreads();
    float mu = mu_s;
    float d = x - mu;
    float s2 = d * d;
#pragma unroll
    for (int o = 16; o; o >>= 1) s2 += __shfl_down_sync(0xffffffffu, s2, o);
    if (!lane) red[warp] = s2;
    __syncthreads();
    if (tid == 0) {
        float t = 0.0f;
#pragma unroll
        for (int i = 0; i < 16; i++) t += red[i];
        rs_s = rsqrtf(t * (1.0f / DM) + 1e-5f);
    }
    __syncthreads();
    out[(size_t)row * DM + tid] = d * rs_s * gamma[tid] + beta[tid];
}

// ---------------- launch ---------------------------------------------------------
extern "C" void kernel_launch(void* const* d_in, const int* in_sizes, int n_in,
                              void* d_out, int out_size) {
    const float* pos   = (const float*)d_in[0];
    const float* feat  = (const float*)d_in[1];
    // d_in[2] = k_neighbors (compile-time 16)
    const float* Wq    = (const float*)d_in[3];
    const float* Wk    = (const float*)d_in[4];
    const float* Wv    = (const float*)d_in[5];
    const float* Wo    = (const float*)d_in[6];
    const float* bo    = (const float*)d_in[7];
    const float* Wpos  = (const float*)d_in[8];
    const float* bpos  = (const float*)d_in[9];
    const float* temp  = (const float*)d_in[10];
    const float* gamma = (const float*)d_in[11];
    const float* beta  = (const float*)d_in[12];
    float* out = (float*)d_out;

    float *pQ, *pK, *pV, *pAtt, *pTmp;
    cudaGetSymbolAddress((void**)&pQ,   g_Q);
    cudaGetSymbolAddress((void**)&pK,   g_K);
    cudaGetSymbolAddress((void**)&pV,   g_V);
    cudaGetSymbolAddress((void**)&pAtt, g_att);
    cudaGetSymbolAddress((void**)&pTmp, g_tmp);

    knn_kernel<<<ROWS / 128, 128>>>(pos);

    dim3 ggrid(DM / BN, ROWS / BM);
    gemm_kernel<<<ggrid, 256>>>(feat, Wq, pQ, ROWS, DM, DM);
    gemm_kernel<<<ggrid, 256>>>(feat, Wk, pK, ROWS, DM, DM);
    gemm_kernel<<<ggrid, 256>>>(feat, Wv, pV, ROWS, DM, DM);

    attn_kernel<<<ROWS, 512>>>(nullptr, pos, Wpos, bpos, temp);

    gemm_kernel<<<ggrid, 256>>>(pAtt, Wo, pTmp, ROWS, DM, DM);

    ln_kernel<<<ROWS, 512>>>(feat, bo, gamma, beta, out);
}

// round 2
// speedup vs baseline: 1.3863x; 1.3863x over previous
#include <cuda_runtime.h>
#include <cuda_bf16.h>
#include <math.h>

#define BATCH 2
#define NPTS 4096
#define DM 512
#define NH 8
#define DH 64
#define KNB 16
#define ROWS (BATCH * NPTS)   // 8192

// ---------------- scratch (device globals; no allocation allowed) ----------------
__device__ float g_Q[ROWS * DM];
__device__ float g_K[ROWS * DM];
__device__ float g_V[ROWS * DM];
__device__ float g_att[ROWS * DM];
__device__ float g_tmp[ROWS * DM];
__device__ int   g_idx[ROWS * KNB];

// ---------------- kNN: warp per query, packed-u64 keys, sorted-17 + merge --------
// key = (float_bits(dist) << 32) | index  -> ascending u64 order == top_k order
// (dist >= 0 so float bits are monotone; tie on dist -> smaller index first,
//  matching jax.lax.top_k's stable tie-break.)
#define QW 8   // queries (warps) per block
__global__ __launch_bounds__(256) void knn_kernel(const float* __restrict__ pos) {
    __shared__ unsigned long long smrg[QW][32][KNB + 2];   // +1 sentinel, +1 pad
    int warp = threadIdx.x >> 5, lane = threadIdx.x & 31;
    int q = blockIdx.x * QW + warp;                         // 0..8191
    int b = q >> 12;
    int n = q & (NPTS - 1);
    const float* pb = pos + (size_t)b * NPTS * 3;
    float qx = pb[n * 3 + 0], qy = pb[n * 3 + 1], qz = pb[n * 3 + 2];

    unsigned long long key[KNB + 1];
#pragma unroll
    for (int i = 0; i < KNB + 1; i++) key[i] = 0xFFFFFFFFFFFFFFFFull;

    for (int step = 0; step < NPTS / 32; step++) {
        int j = step * 32 + lane;
        float dx = qx - __ldg(&pb[j * 3 + 0]);
        float dy = qy - __ldg(&pb[j * 3 + 1]);
        float dz = qz - __ldg(&pb[j * 3 + 2]);
        float d = fmaf(dx, dx, fmaf(dy, dy, dz * dz));
        unsigned long long kk =
            ((unsigned long long)__float_as_uint(d) << 32) | (unsigned)j;
        if (kk < key[KNB]) {
            bool done = false;
#pragma unroll
            for (int p = KNB; p >= 0; p--) {
                if (!done) {
                    bool shift = (p > 0) && (kk < key[p - 1]);
                    if (shift) key[p] = key[p - 1];
                    else       { key[p] = kk; done = true; }
                }
            }
        }
    }

    // stage sorted per-lane lists in shared (dynamic head index needs memory)
#pragma unroll
    for (int i = 0; i < KNB + 1; i++) smrg[warp][lane][i] = key[i];
    smrg[warp][lane][KNB + 1] = 0xFFFFFFFFFFFFFFFFull;      // sentinel
    __syncwarp();

    // 17-round selection merge: pop global min each round.
    // Round 0 pops the self point (dist==0, unique) -> dropped.
    int p = 0;
    unsigned long long head = smrg[warp][lane][0];
    for (int out = 0; out < KNB + 1; out++) {
        unsigned long long m = head;
#pragma unroll
        for (int off = 16; off; off >>= 1) {
            unsigned long long o = __shfl_xor_sync(0xffffffffu, m, off);
            if (o < m) m = o;
        }
        if (out > 0 && lane == 0)
            g_idx[q * KNB + out - 1] = (int)(unsigned)m;    // low 32 bits = index
        if (head == m) { p++; head = smrg[warp][lane][p]; } // keys unique -> 1 winner
    }
}

// ---------------- SGEMM: C(MxN) = A(MxK) * B(KxN), all row-major, fp32 -----------
#define BM 128
#define BN 128
#define BKK 16

__device__ __forceinline__ void gemm_body(const float* __restrict__ A,
                                          const float* __restrict__ B,
                                          float* __restrict__ C,
                                          int M, int N, int K,
                                          int bm, int bn) {
    __shared__ float As[BKK][BM];
    __shared__ float Bs[BKK][BN];
    int tid = threadIdx.x;             // 256
    int tx = tid & 15, ty = tid >> 4;  // 16 x 16

    float acc[8][8];
#pragma unroll
    for (int i = 0; i < 8; i++)
#pragma unroll
        for (int j = 0; j < 8; j++) acc[i][j] = 0.0f;

    for (int k0 = 0; k0 < K; k0 += BKK) {
#pragma unroll
        for (int i = 0; i < 2; i++) {
            int v = i * 256 + tid;
            int r  = v >> 2;
            int c4 = (v & 3) << 2;
            float4 a = *(const float4*)&A[(size_t)(bm + r) * K + k0 + c4];
            As[c4 + 0][r] = a.x;
            As[c4 + 1][r] = a.y;
            As[c4 + 2][r] = a.z;
            As[c4 + 3][r] = a.w;
            int rb  = v >> 5;
            int cb4 = (v & 31) << 2;
            *(float4*)&Bs[rb][cb4] = *(const float4*)&B[(size_t)(k0 + rb) * N + bn + cb4];
        }
        __syncthreads();
#pragma unroll
        for (int kk = 0; kk < BKK; kk++) {
            float a[8], bf[8];
            *(float4*)&a[0]  = *(const float4*)&As[kk][ty * 8 + 0];
            *(float4*)&a[4]  = *(const float4*)&As[kk][ty * 8 + 4];
            *(float4*)&bf[0] = *(const float4*)&Bs[kk][tx * 8 + 0];
            *(float4*)&bf[4] = *(const float4*)&Bs[kk][tx * 8 + 4];
#pragma unroll
            for (int i = 0; i < 8; i++)
#pragma unroll
                for (int j = 0; j < 8; j++)
                    acc[i][j] = fmaf(a[i], bf[j], acc[i][j]);
        }
        __syncthreads();
    }
#pragma unroll
    for (int i = 0; i < 8; i++) {
        int r = bm + ty * 8 + i;
#pragma unroll
        for (int j = 0; j < 8; j += 4) {
            float4 o = make_float4(acc[i][j], acc[i][j + 1], acc[i][j + 2], acc[i][j + 3]);
            *(float4*)&C[(size_t)r * N + bn + tx * 8 + j] = o;
        }
    }
}

__global__ __launch_bounds__(256) void gemm_kernel(const float* __restrict__ A,
                                                   const float* __restrict__ B,
                                                   float* __restrict__ C,
                                                   int M, int N, int K) {
    gemm_body(A, B, C, M, N, K, blockIdx.y * BM, blockIdx.x * BN);
}

// fused Q/K/V: blockIdx.z selects weight + destination
__global__ __launch_bounds__(256) void gemm_qkv_kernel(const float* __restrict__ A,
                                                       const float* __restrict__ Bq,
                                                       const float* __restrict__ Bk,
                                                       const float* __restrict__ Bv,
                                                       float* __restrict__ Cq,
                                                       float* __restrict__ Ck,
                                                       float* __restrict__ Cv) {
    const float* B = (blockIdx.z == 0) ? Bq : (blockIdx.z == 1) ? Bk : Bv;
    float*       C = (blockIdx.z == 0) ? Cq : (blockIdx.z == 1) ? Ck : Cv;
    gemm_body(A, B, C, ROWS, DM, DM, blockIdx.y * BM, blockIdx.x * BN);
}

// ---------------- attention: one block per (b, n), 512 threads -------------------
__global__ __launch_bounds__(512) void attn_kernel(const float* __restrict__ pos,
                                                   const float* __restrict__ Wpos,
                                                   const float* __restrict__ bpos,
                                                   const float* __restrict__ temp) {
    int row = blockIdx.x;          // b*4096 + n
    int b = row >> 12;
    int n = row & (NPTS - 1);
    int tid = threadIdx.x;         // 0..511
    int dd = tid & (DH - 1);       // dim within head
    int h  = tid >> 6;
    int warp = tid >> 5, lane = tid & 31;

    __shared__ float sv[KNB][DM];     // 32 KB: gathered V rows
    __shared__ float spart[KNB][16];  // per-warp score partials
    __shared__ float sw[NH][KNB];     // softmax weights

    float invT = 1.0f / temp[0];
    float qv = g_Q[(size_t)row * DM + tid] * invT;
    // pe uses only Wpos[:, :64] and bpos[:64]  (tile(...,4)[..., :64])
    float w0 = Wpos[0 * 128 + dd];
    float w1 = Wpos[1 * 128 + dd];
    float w2 = Wpos[2 * 128 + dd];
    float bp = bpos[dd];
    const float* posb = pos + (size_t)b * NPTS * 3;
    float px = posb[n * 3 + 0], py = posb[n * 3 + 1], pz = posb[n * 3 + 2];

#pragma unroll
    for (int k = 0; k < KNB; k++) {
        int j = g_idx[row * KNB + k];
        int kv = (b << 12) + j;
        float kval = g_K[(size_t)kv * DM + tid];
        float rx = px - posb[j * 3 + 0];
        float ry = py - posb[j * 3 + 1];
        float rz = pz - posb[j * 3 + 2];
        float pe = fmaf(rx, w0, fmaf(ry, w1, fmaf(rz, w2, bp)));
        float prod = qv * (kval + pe);
#pragma unroll
        for (int off = 16; off; off >>= 1)
            prod += __shfl_down_sync(0xffffffffu, prod, off);
        if (lane == 0) spart[k][warp] = prod;
        sv[k][tid] = g_V[(size_t)kv * DM + tid];
    }
    __syncthreads();

    if (tid < NH) {  // one thread per head does the softmax
        float s[KNB];
        float m = -INFINITY;
#pragma unroll
        for (int k = 0; k < KNB; k++) {
            s[k] = spart[k][2 * tid] + spart[k][2 * tid + 1];
            m = fmaxf(m, s[k]);
        }
        float sum = 0.0f;
#pragma unroll
        for (int k = 0; k < KNB; k++) { s[k] = __expf(s[k] - m); sum += s[k]; }
        float inv = 1.0f / sum;
#pragma unroll
        for (int k = 0; k < KNB; k++) sw[tid][k] = s[k] * inv;
    }
    __syncthreads();

    float acc = 0.0f;
#pragma unroll
    for (int k = 0; k < KNB; k++)
        acc = fmaf(sw[h][k], sv[k][tid], acc);
    g_att[(size_t)row * DM + tid] = acc;
}

// ---------------- epilogue: +bo, +residual, LayerNorm ----------------------------
__global__ __launch_bounds__(512) void ln_kernel(const float* __restrict__ feat,
                                                 const float* __restrict__ bo,
                                                 const float* __restrict__ gamma,
                                                 const float* __restrict__ beta,
                                                 float* __restrict__ out) {
    int row = blockIdx.x;
    int tid = threadIdx.x;  // 512
    int lane = tid & 31, warp = tid >> 5;
    __shared__ float red[16];
    __shared__ float mu_s, rs_s;

    float x = g_tmp[(size_t)row * DM + tid] + bo[tid] + feat[(size_t)row * DM + tid];

    float s = x;
#pragma unroll
    for (int o = 16; o; o >>= 1) s += __shfl_down_sync(0xffffffffu, s, o);
    if (!lane) red[warp] = s;
    __syncthreads();
    if (tid == 0) {
        float t = 0.0f;
#pragma unroll
        for (int i = 0; i < 16; i++) t += red[i];
        mu_s = t * (1.0f / DM);
    }
    __syncthreads();
    float mu = mu_s;
    float d = x - mu;
    float s2 = d * d;
#pragma unroll
    for (int o = 16; o; o >>= 1) s2 += __shfl_down_sync(0xffffffffu, s2, o);
    if (!lane) red[warp] = s2;
    __syncthreads();
    if (tid == 0) {
        float t = 0.0f;
#pragma unroll
        for (int i = 0; i < 16; i++) t += red[i];
        rs_s = rsqrtf(t * (1.0f / DM) + 1e-5f);
    }
    __syncthreads();
    out[(size_t)row * DM + tid] = d * rs_s * gamma[tid] + beta[tid];
}

// ---------------- launch ---------------------------------------------------------
extern "C" void kernel_launch(void* const* d_in, const int* in_sizes, int n_in,
                              void* d_out, int out_size) {
    const float* pos   = (const float*)d_in[0];
    const float* feat  = (const float*)d_in[1];
    // d_in[2] = k_neighbors (compile-time 16)
    const float* Wq    = (const float*)d_in[3];
    const float* Wk    = (const float*)d_in[4];
    const float* Wv    = (const float*)d_in[5];
    const float* Wo    = (const float*)d_in[6];
    const float* bo    = (const float*)d_in[7];
    const float* Wpos  = (const float*)d_in[8];
    const float* bpos  = (const float*)d_in[9];
    const float* temp  = (const float*)d_in[10];
    const float* gamma = (const float*)d_in[11];
    const float* beta  = (const float*)d_in[12];
    float* out = (float*)d_out;

    float *pQ, *pK, *pV, *pAtt, *pTmp;
    cudaGetSymbolAddress((void**)&pQ,   g_Q);
    cudaGetSymbolAddress((void**)&pK,   g_K);
    cudaGetSymbolAddress((void**)&pV,   g_V);
    cudaGetSymbolAddress((void**)&pAtt, g_att);
    cudaGetSymbolAddress((void**)&pTmp, g_tmp);

    knn_kernel<<<ROWS / QW, 256>>>(pos);

    dim3 qkv_grid(DM / BN, ROWS / BM, 3);
    gemm_qkv_kernel<<<qkv_grid, 256>>>(feat, Wq, Wk, Wv, pQ, pK, pV);

    attn_kernel<<<ROWS, 512>>>(pos, Wpos, bpos, temp);

    dim3 ggrid(DM / BN, ROWS / BM);
    gemm_kernel<<<ggrid, 256>>>(pAtt, Wo, pTmp, ROWS, DM, DM);

    ln_kernel<<<ROWS, 512>>>(feat, bo, gamma, beta, out);
}

// round 3
// speedup vs baseline: 1.4527x; 1.0480x over previous
#include <cuda_runtime.h>
#include <cuda_bf16.h>
#include <math.h>

#define BATCH 2
#define NPTS 4096
#define DM 512
#define NH 8
#define DH 64
#define KNB 16
#define ROWS (BATCH * NPTS)   // 8192

// ---------------- scratch (device globals; no allocation allowed) ----------------
__device__ float g_Q[ROWS * DM];
__device__ float g_K[ROWS * DM];
__device__ float g_V[ROWS * DM];
__device__ float g_att[ROWS * DM];
__device__ float g_tmp[ROWS * DM];
__device__ int   g_idx[ROWS * KNB];

// ---------------- packed f32x2 helpers (Blackwell FFMA2) -------------------------
__device__ __forceinline__ unsigned long long pk2(float lo, float hi) {
    unsigned long long r;
    asm("mov.b64 %0, {%1, %2};" : "=l"(r) : "f"(lo), "f"(hi));
    return r;
}
__device__ __forceinline__ unsigned long long fma2(unsigned long long a,
                                                   unsigned long long b,
                                                   unsigned long long c) {
    unsigned long long d;
    asm("fma.rn.f32x2 %0, %1, %2, %3;" : "=l"(d) : "l"(a), "l"(b), "l"(c));
    return d;
}
__device__ __forceinline__ float2 unpk2(unsigned long long v) {
    float2 f;
    asm("mov.b64 {%0, %1}, %2;" : "=f"(f.x), "=f"(f.y) : "l"(v));
    return f;
}

// ---------------- kNN: warp per query, packed-u64 keys, sorted-17 + merge --------
#define QW 8   // queries (warps) per block
__global__ __launch_bounds__(256) void knn_kernel(const float* __restrict__ pos) {
    __shared__ unsigned long long smrg[QW][32][KNB + 2];
    int warp = threadIdx.x >> 5, lane = threadIdx.x & 31;
    int q = blockIdx.x * QW + warp;
    int b = q >> 12;
    int n = q & (NPTS - 1);
    const float* pb = pos + (size_t)b * NPTS * 3;
    float qx = pb[n * 3 + 0], qy = pb[n * 3 + 1], qz = pb[n * 3 + 2];

    unsigned long long key[KNB + 1];
#pragma unroll
    for (int i = 0; i < KNB + 1; i++) key[i] = 0xFFFFFFFFFFFFFFFFull;

    for (int step = 0; step < NPTS / 32; step++) {
        int j = step * 32 + lane;
        float dx = qx - __ldg(&pb[j * 3 + 0]);
        float dy = qy - __ldg(&pb[j * 3 + 1]);
        float dz = qz - __ldg(&pb[j * 3 + 2]);
        float d = fmaf(dx, dx, fmaf(dy, dy, dz * dz));
        unsigned long long kk =
            ((unsigned long long)__float_as_uint(d) << 32) | (unsigned)j;
        if (kk < key[KNB]) {
            bool done = false;
#pragma unroll
            for (int p = KNB; p >= 0; p--) {
                if (!done) {
                    bool shift = (p > 0) && (kk < key[p - 1]);
                    if (shift) key[p] = key[p - 1];
                    else       { key[p] = kk; done = true; }
                }
            }
        }
    }

#pragma unroll
    for (int i = 0; i < KNB + 1; i++) smrg[warp][lane][i] = key[i];
    smrg[warp][lane][KNB + 1] = 0xFFFFFFFFFFFFFFFFull;
    __syncwarp();

    int p = 0;
    unsigned long long head = smrg[warp][lane][0];
    for (int out = 0; out < KNB + 1; out++) {
        unsigned long long m = head;
#pragma unroll
        for (int off = 16; off; off >>= 1) {
            unsigned long long o = __shfl_xor_sync(0xffffffffu, m, off);
            if (o < m) m = o;
        }
        if (out > 0 && lane == 0)
            g_idx[q * KNB + out - 1] = (int)(unsigned)m;
        if (head == m) { p++; head = smrg[warp][lane][p]; }
    }
}

// ---------------- SGEMM with packed f32x2 accumulation ---------------------------
#define BM 128
#define BN 128
#define BKK 16

__device__ __forceinline__ void gemm_body(const float* __restrict__ A,
                                          const float* __restrict__ B,
                                          float* __restrict__ C,
                                          int M, int N, int K,
                                          int bm, int bn) {
    __shared__ float As[BKK][BM];
    __shared__ float Bs[BKK][BN];
    int tid = threadIdx.x;             // 256
    int tx = tid & 15, ty = tid >> 4;  // 16 x 16

    // acc2[ip][j]: lo = C[2ip][j], hi = C[2ip+1][j]  (rows within 8-row micro-tile)
    unsigned long long acc2[4][8];
#pragma unroll
    for (int i = 0; i < 4; i++)
#pragma unroll
        for (int j = 0; j < 8; j++) acc2[i][j] = 0ull;

    for (int k0 = 0; k0 < K; k0 += BKK) {
#pragma unroll
        for (int i = 0; i < 2; i++) {
            int v = i * 256 + tid;
            int r  = v >> 2;
            int c4 = (v & 3) << 2;
            float4 a = *(const float4*)&A[(size_t)(bm + r) * K + k0 + c4];
            As[c4 + 0][r] = a.x;
            As[c4 + 1][r] = a.y;
            As[c4 + 2][r] = a.z;
            As[c4 + 3][r] = a.w;
            int rb  = v >> 5;
            int cb4 = (v & 31) << 2;
            *(float4*)&Bs[rb][cb4] = *(const float4*)&B[(size_t)(k0 + rb) * N + bn + cb4];
        }
        __syncthreads();
#pragma unroll
        for (int kk = 0; kk < BKK; kk++) {
            float4 a0 = *(const float4*)&As[kk][ty * 8 + 0];
            float4 a1 = *(const float4*)&As[kk][ty * 8 + 4];
            float4 b0 = *(const float4*)&Bs[kk][tx * 8 + 0];
            float4 b1 = *(const float4*)&Bs[kk][tx * 8 + 4];
            unsigned long long ap[4];
            ap[0] = pk2(a0.x, a0.y);
            ap[1] = pk2(a0.z, a0.w);
            ap[2] = pk2(a1.x, a1.y);
            ap[3] = pk2(a1.z, a1.w);
            unsigned long long bd[8];
            bd[0] = pk2(b0.x, b0.x); bd[1] = pk2(b0.y, b0.y);
            bd[2] = pk2(b0.z, b0.z); bd[3] = pk2(b0.w, b0.w);
            bd[4] = pk2(b1.x, b1.x); bd[5] = pk2(b1.y, b1.y);
            bd[6] = pk2(b1.z, b1.z); bd[7] = pk2(b1.w, b1.w);
#pragma unroll
            for (int ip = 0; ip < 4; ip++)
#pragma unroll
                for (int j = 0; j < 8; j++)
                    acc2[ip][j] = fma2(ap[ip], bd[j], acc2[ip][j]);
        }
        __syncthreads();
    }
#pragma unroll
    for (int ip = 0; ip < 4; ip++) {
        float lo[8], hi[8];
#pragma unroll
        for (int j = 0; j < 8; j++) {
            float2 u = unpk2(acc2[ip][j]);
            lo[j] = u.x; hi[j] = u.y;
        }
        int r0 = bm + ty * 8 + 2 * ip;
#pragma unroll
        for (int j = 0; j < 8; j += 4) {
            *(float4*)&C[(size_t)r0 * N + bn + tx * 8 + j] =
                make_float4(lo[j], lo[j + 1], lo[j + 2], lo[j + 3]);
            *(float4*)&C[(size_t)(r0 + 1) * N + bn + tx * 8 + j] =
                make_float4(hi[j], hi[j + 1], hi[j + 2], hi[j + 3]);
        }
    }
}

__global__ __launch_bounds__(256) void gemm_kernel(const float* __restrict__ A,
                                                   const float* __restrict__ B,
                                                   float* __restrict__ C,
                                                   int M, int N, int K) {
    gemm_body(A, B, C, M, N, K, blockIdx.y * BM, blockIdx.x * BN);
}

__global__ __launch_bounds__(256) void gemm_qkv_kernel(const float* __restrict__ A,
                                                       const float* __restrict__ Bq,
                                                       const float* __restrict__ Bk,
                                                       const float* __restrict__ Bv,
                                                       float* __restrict__ Cq,
                                                       float* __restrict__ Ck,
                                                       float* __restrict__ Cv) {
    const float* B = (blockIdx.z == 0) ? Bq : (blockIdx.z == 1) ? Bk : Bv;
    float*       C = (blockIdx.z == 0) ? Cq : (blockIdx.z == 1) ? Ck : Cv;
    gemm_body(A, B, C, ROWS, DM, DM, blockIdx.y * BM, blockIdx.x * BN);
}

// ---------------- attention: warp per (row, head), no smem, no barriers ----------
__global__ __launch_bounds__(256) void attn_kernel(const float* __restrict__ pos,
                                                   const float* __restrict__ Wpos,
                                                   const float* __restrict__ bpos,
                                                   const float* __restrict__ temp) {
    int gw   = (blockIdx.x * blockDim.x + threadIdx.x) >> 5;  // 0..65535
    int lane = threadIdx.x & 31;
    int row  = gw >> 3;             // 0..8191
    int h    = gw & 7;
    int b    = row >> 12;
    int n    = row & (NPTS - 1);
    const float* posb = pos + (size_t)b * NPTS * 3;
    int base = (b << 12);

    // lane k (<16) owns neighbor k: its index and relative position
    int j = 0;
    float rx = 0.f, ry = 0.f, rz = 0.f;
    float px = posb[n * 3 + 0], py = posb[n * 3 + 1], pz = posb[n * 3 + 2];
    if (lane < KNB) {
        j  = g_idx[row * KNB + lane];
        rx = px - posb[j * 3 + 0];
        ry = py - posb[j * 3 + 1];
        rz = pz - posb[j * 3 + 2];
    }

    // this lane covers dims d = 2*lane, 2*lane+1 of the head (dd = d mod 64 = d)
    float invT = 1.0f / temp[0];
    float2 q = *(const float2*)&g_Q[(size_t)row * DM + h * DH + 2 * lane];
    q.x *= invT; q.y *= invT;
    float2 w0 = *(const float2*)&Wpos[0 * 128 + 2 * lane];
    float2 w1 = *(const float2*)&Wpos[1 * 128 + 2 * lane];
    float2 w2 = *(const float2*)&Wpos[2 * 128 + 2 * lane];
    float2 bp = *(const float2*)&bpos[2 * lane];

    float myscore = 0.0f;
#pragma unroll
    for (int k = 0; k < KNB; k++) {
        int   jk  = __shfl_sync(0xffffffffu, j,  k);
        float rxk = __shfl_sync(0xffffffffu, rx, k);
        float ryk = __shfl_sync(0xffffffffu, ry, k);
        float rzk = __shfl_sync(0xffffffffu, rz, k);
        float2 kv = *(const float2*)&g_K[(size_t)(base + jk) * DM + h * DH + 2 * lane];
        float pex = fmaf(rxk, w0.x, fmaf(ryk, w1.x, fmaf(rzk, w2.x, bp.x)));
        float pey = fmaf(rxk, w0.y, fmaf(ryk, w1.y, fmaf(rzk, w2.y, bp.y)));
        float s = fmaf(q.x, kv.x + pex, q.y * (kv.y + pey));
#pragma unroll
        for (int off = 16; off; off >>= 1)
            s += __shfl_xor_sync(0xffffffffu, s, off);
        if (lane == k) myscore = s;
    }

    // softmax across lanes 0..15 (xor offsets stay within the 16-lane group)
    float sc = (lane < KNB) ? myscore : -INFINITY;
    float m = sc;
#pragma unroll
    for (int off = 8; off; off >>= 1)
        m = fmaxf(m, __shfl_xor_sync(0xffffffffu, m, off));
    float e = (lane < KNB) ? __expf(sc - m) : 0.0f;
    float sum = e;
#pragma unroll
    for (int off = 8; off; off >>= 1)
        sum += __shfl_xor_sync(0xffffffffu, sum, off);
    float w = e / sum;

    // output accumulation
    float2 acc = make_float2(0.f, 0.f);
#pragma unroll
    for (int k = 0; k < KNB; k++) {
        float wk = __shfl_sync(0xffffffffu, w, k);
        int   jk = __shfl_sync(0xffffffffu, j, k);
        float2 v = *(const float2*)&g_V[(size_t)(base + jk) * DM + h * DH + 2 * lane];
        acc.x = fmaf(wk, v.x, acc.x);
        acc.y = fmaf(wk, v.y, acc.y);
    }
    *(float2*)&g_att[(size_t)row * DM + h * DH + 2 * lane] = acc;
}

// ---------------- epilogue: +bo, +residual, LayerNorm ----------------------------
__global__ __launch_bounds__(512) void ln_kernel(const float* __restrict__ feat,
                                                 const float* __restrict__ bo,
                                                 const float* __restrict__ gamma,
                                                 const float* __restrict__ beta,
                                                 float* __restrict__ out) {
    int row = blockIdx.x;
    int tid = threadIdx.x;  // 512
    int lane = tid & 31, warp = tid >> 5;
    __shared__ float red[16];
    __shared__ float mu_s, rs_s;

    float x = g_tmp[(size_t)row * DM + tid] + bo[tid] + feat[(size_t)row * DM + tid];

    float s = x;
#pragma unroll
    for (int o = 16; o; o >>= 1) s += __shfl_down_sync(0xffffffffu, s, o);
    if (!lane) red[warp] = s;
    __syncthreads();
    if (tid == 0) {
        float t = 0.0f;
#pragma unroll
        for (int i = 0; i < 16; i++) t += red[i];
        mu_s = t * (1.0f / DM);
    }
    __syncthreads();
    float mu = mu_s;
    float d = x - mu;
    float s2 = d * d;
#pragma unroll
    for (int o = 16; o; o >>= 1) s2 += __shfl_down_sync(0xffffffffu, s2, o);
    if (!lane) red[warp] = s2;
    __syncthreads();
    if (tid == 0) {
        float t = 0.0f;
#pragma unroll
        for (int i = 0; i < 16; i++) t += red[i];
        rs_s = rsqrtf(t * (1.0f / DM) + 1e-5f);
    }
    __syncthreads();
    out[(size_t)row * DM + tid] = d * rs_s * gamma[tid] + beta[tid];
}

// ---------------- launch ---------------------------------------------------------
extern "C" void kernel_launch(void* const* d_in, const int* in_sizes, int n_in,
                              void* d_out, int out_size) {
    const float* pos   = (const float*)d_in[0];
    const float* feat  = (const float*)d_in[1];
    const float* Wq    = (const float*)d_in[3];
    const float* Wk    = (const float*)d_in[4];
    const float* Wv    = (const float*)d_in[5];
    const float* Wo    = (const float*)d_in[6];
    const float* bo    = (const float*)d_in[7];
    const float* Wpos  = (const float*)d_in[8];
    const float* bpos  = (const float*)d_in[9];
    const float* temp  = (const float*)d_in[10];
    const float* gamma = (const float*)d_in[11];
    const float* beta  = (const float*)d_in[12];
    float* out = (float*)d_out;

    float *pQ, *pK, *pV, *pAtt, *pTmp;
    cudaGetSymbolAddress((void**)&pQ,   g_Q);
    cudaGetSymbolAddress((void**)&pK,   g_K);
    cudaGetSymbolAddress((void**)&pV,   g_V);
    cudaGetSymbolAddress((void**)&pAtt, g_att);
    cudaGetSymbolAddress((void**)&pTmp, g_tmp);

    knn_kernel<<<ROWS / QW, 256>>>(pos);

    dim3 qkv_grid(DM / BN, ROWS / BM, 3);
    gemm_qkv_kernel<<<qkv_grid, 256>>>(feat, Wq, Wk, Wv, pQ, pK, pV);

    attn_kernel<<<ROWS * NH * 32 / 256, 256>>>(pos, Wpos, bpos, temp);

    dim3 ggrid(DM / BN, ROWS / BM);
    gemm_kernel<<<ggrid, 256>>>(pAtt, Wo, pTmp, ROWS, DM, DM);

    ln_kernel<<<ROWS, 512>>>(feat, bo, gamma, beta, out);
}

// round 4
// speedup vs baseline: 2.0691x; 1.4243x over previous
#include <cuda_runtime.h>
#include <cuda_bf16.h>
#include <math.h>

#define BATCH 2
#define NPTS 4096
#define DM 512
#define NH 8
#define DH 64
#define KNB 16
#define ROWS (BATCH * NPTS)   // 8192

// ---------------- scratch (device globals; no allocation allowed) ----------------
__device__ float g_Q[ROWS * DM];
__device__ float g_K[ROWS * DM];
__device__ float g_V[ROWS * DM];
__device__ float g_att[ROWS * DM];
__device__ float g_tmp[ROWS * DM];
__device__ int   g_idx[ROWS * KNB];

// ---------------- kNN: warp per query, branch-free sorted top-17 -----------------
// key = (float_bits(dist) << 32) | index  -> ascending u64 order == top_k order
#define QW 8   // queries (warps) per block
__global__ __launch_bounds__(256) void knn_kernel(const float* __restrict__ pos) {
    __shared__ unsigned long long smrg[QW][32][KNB + 2];
    int warp = threadIdx.x >> 5, lane = threadIdx.x & 31;
    int q = blockIdx.x * QW + warp;
    int b = q >> 12;
    int n = q & (NPTS - 1);
    const float* pb = pos + (size_t)b * NPTS * 3;
    float qx = pb[n * 3 + 0], qy = pb[n * 3 + 1], qz = pb[n * 3 + 2];

    unsigned long long key[KNB + 1];
#pragma unroll
    for (int i = 0; i < KNB + 1; i++) key[i] = 0xFFFFFFFFFFFFFFFFull;

    for (int step = 0; step < NPTS / 32; step++) {
        int j = step * 32 + lane;
        float dx = qx - __ldg(&pb[j * 3 + 0]);
        float dy = qy - __ldg(&pb[j * 3 + 1]);
        float dz = qz - __ldg(&pb[j * 3 + 2]);
        float d = fmaf(dx, dx, fmaf(dy, dy, dz * dz));
        unsigned long long kk =
            ((unsigned long long)__float_as_uint(d) << 32) | (unsigned)j;
        if (kk < key[KNB]) {
            // branch-free sorted insert: descending, pure select chain
#pragma unroll
            for (int p = KNB; p >= 1; p--) {
                unsigned long long lower = key[p - 1];
                unsigned long long cur   = key[p];
                key[p] = (kk >= cur) ? cur : ((kk >= lower) ? kk : lower);
            }
            key[0] = (kk < key[0]) ? kk : key[0];
        }
    }

#pragma unroll
    for (int i = 0; i < KNB + 1; i++) smrg[warp][lane][i] = key[i];
    smrg[warp][lane][KNB + 1] = 0xFFFFFFFFFFFFFFFFull;
    __syncwarp();

    // 17-round selection merge; round 0 pops the self point (dist==0) -> dropped
    int p = 0;
    unsigned long long head = smrg[warp][lane][0];
    for (int out = 0; out < KNB + 1; out++) {
        unsigned long long m = head;
#pragma unroll
        for (int off = 16; off; off >>= 1) {
            unsigned long long o = __shfl_xor_sync(0xffffffffu, m, off);
            if (o < m) m = o;
        }
        if (out > 0 && lane == 0)
            g_idx[q * KNB + out - 1] = (int)(unsigned)m;
        if (head == m) { p++; head = smrg[warp][lane][p]; }
    }
}

// ---------------- SGEMM: C(MxN) = A(MxK) * B(KxN), all row-major, fp32 -----------
#define BM 128
#define BN 128
#define BKK 16

__device__ __forceinline__ void gemm_body(const float* __restrict__ A,
                                          const float* __restrict__ B,
                                          float* __restrict__ C,
                                          int M, int N, int K,
                                          int bm, int bn) {
    __shared__ float As[BKK][BM];
    __shared__ float Bs[BKK][BN];
    int tid = threadIdx.x;             // 256
    int tx = tid & 15, ty = tid >> 4;  // 16 x 16

    float acc[8][8];
#pragma unroll
    for (int i = 0; i < 8; i++)
#pragma unroll
        for (int j = 0; j < 8; j++) acc[i][j] = 0.0f;

    for (int k0 = 0; k0 < K; k0 += BKK) {
#pragma unroll
        for (int i = 0; i < 2; i++) {
            int v = i * 256 + tid;
            int r  = v >> 2;
            int c4 = (v & 3) << 2;
            float4 a = *(const float4*)&A[(size_t)(bm + r) * K + k0 + c4];
            As[c4 + 0][r] = a.x;
            As[c4 + 1][r] = a.y;
            As[c4 + 2][r] = a.z;
            As[c4 + 3][r] = a.w;
            int rb  = v >> 5;
            int cb4 = (v & 31) << 2;
            *(float4*)&Bs[rb][cb4] = *(const float4*)&B[(size_t)(k0 + rb) * N + bn + cb4];
        }
        __syncthreads();
#pragma unroll
        for (int kk = 0; kk < BKK; kk++) {
            float a[8], bf[8];
            *(float4*)&a[0]  = *(const float4*)&As[kk][ty * 8 + 0];
            *(float4*)&a[4]  = *(const float4*)&As[kk][ty * 8 + 4];
            *(float4*)&bf[0] = *(const float4*)&Bs[kk][tx * 8 + 0];
            *(float4*)&bf[4] = *(const float4*)&Bs[kk][tx * 8 + 4];
#pragma unroll
            for (int i = 0; i < 8; i++)
#pragma unroll
                for (int j = 0; j < 8; j++)
                    acc[i][j] = fmaf(a[i], bf[j], acc[i][j]);
        }
        __syncthreads();
    }
#pragma unroll
    for (int i = 0; i < 8; i++) {
        int r = bm + ty * 8 + i;
#pragma unroll
        for (int j = 0; j < 8; j += 4) {
            float4 o = make_float4(acc[i][j], acc[i][j + 1], acc[i][j + 2], acc[i][j + 3]);
            *(float4*)&C[(size_t)r * N + bn + tx * 8 + j] = o;
        }
    }
}

__global__ __launch_bounds__(256) void gemm_kernel(const float* __restrict__ A,
                                                   const float* __restrict__ B,
                                                   float* __restrict__ C,
                                                   int M, int N, int K) {
    gemm_body(A, B, C, M, N, K, blockIdx.y * BM, blockIdx.x * BN);
}

__global__ __launch_bounds__(256) void gemm_qkv_kernel(const float* __restrict__ A,
                                                       const float* __restrict__ Bq,
                                                       const float* __restrict__ Bk,
                                                       const float* __restrict__ Bv,
                                                       float* __restrict__ Cq,
                                                       float* __restrict__ Ck,
                                                       float* __restrict__ Cv) {
    const float* B = (blockIdx.z == 0) ? Bq : (blockIdx.z == 1) ? Bk : Bv;
    float*       C = (blockIdx.z == 0) ? Cq : (blockIdx.z == 1) ? Ck : Cv;
    gemm_body(A, B, C, ROWS, DM, DM, blockIdx.y * BM, blockIdx.x * BN);
}

// ---------------- attention: warp per (row, head), no smem, no barriers ----------
__global__ __launch_bounds__(256) void attn_kernel(const float* __restrict__ pos,
                                                   const float* __restrict__ Wpos,
                                                   const float* __restrict__ bpos,
                                                   const float* __restrict__ temp) {
    int gw   = (blockIdx.x * blockDim.x + threadIdx.x) >> 5;  // 0..65535
    int lane = threadIdx.x & 31;
    int row  = gw >> 3;             // 0..8191
    int h    = gw & 7;
    int b    = row >> 12;
    int n    = row & (NPTS - 1);
    const float* posb = pos + (size_t)b * NPTS * 3;
    int base = (b << 12);

    int j = 0;
    float rx = 0.f, ry = 0.f, rz = 0.f;
    float px = posb[n * 3 + 0], py = posb[n * 3 + 1], pz = posb[n * 3 + 2];
    if (lane < KNB) {
        j  = g_idx[row * KNB + lane];
        rx = px - posb[j * 3 + 0];
        ry = py - posb[j * 3 + 1];
        rz = pz - posb[j * 3 + 2];
    }

    float invT = 1.0f / temp[0];
    float2 q = *(const float2*)&g_Q[(size_t)row * DM + h * DH + 2 * lane];
    q.x *= invT; q.y *= invT;
    float2 w0 = *(const float2*)&Wpos[0 * 128 + 2 * lane];
    float2 w1 = *(const float2*)&Wpos[1 * 128 + 2 * lane];
    float2 w2 = *(const float2*)&Wpos[2 * 128 + 2 * lane];
    float2 bp = *(const float2*)&bpos[2 * lane];

    float myscore = 0.0f;
#pragma unroll
    for (int k = 0; k < KNB; k++) {
        int   jk  = __shfl_sync(0xffffffffu, j,  k);
        float rxk = __shfl_sync(0xffffffffu, rx, k);
        float ryk = __shfl_sync(0xffffffffu, ry, k);
        float rzk = __shfl_sync(0xffffffffu, rz, k);
        float2 kv = *(const float2*)&g_K[(size_t)(base + jk) * DM + h * DH + 2 * lane];
        float pex = fmaf(rxk, w0.x, fmaf(ryk, w1.x, fmaf(rzk, w2.x, bp.x)));
        float pey = fmaf(rxk, w0.y, fmaf(ryk, w1.y, fmaf(rzk, w2.y, bp.y)));
        float s = fmaf(q.x, kv.x + pex, q.y * (kv.y + pey));
#pragma unroll
        for (int off = 16; off; off >>= 1)
            s += __shfl_xor_sync(0xffffffffu, s, off);
        if (lane == k) myscore = s;
    }

    float sc = (lane < KNB) ? myscore : -INFINITY;
    float m = sc;
#pragma unroll
    for (int off = 8; off; off >>= 1)
        m = fmaxf(m, __shfl_xor_sync(0xffffffffu, m, off));
    float e = (lane < KNB) ? __expf(sc - m) : 0.0f;
    float sum = e;
#pragma unroll
    for (int off = 8; off; off >>= 1)
        sum += __shfl_xor_sync(0xffffffffu, sum, off);
    float w = e / sum;

    float2 acc = make_float2(0.f, 0.f);
#pragma unroll
    for (int k = 0; k < KNB; k++) {
        float wk = __shfl_sync(0xffffffffu, w, k);
        int   jk = __shfl_sync(0xffffffffu, j, k);
        float2 v = *(const float2*)&g_V[(size_t)(base + jk) * DM + h * DH + 2 * lane];
        acc.x = fmaf(wk, v.x, acc.x);
        acc.y = fmaf(wk, v.y, acc.y);
    }
    *(float2*)&g_att[(size_t)row * DM + h * DH + 2 * lane] = acc;
}

// ---------------- epilogue: +bo, +residual, LayerNorm ----------------------------
__global__ __launch_bounds__(512) void ln_kernel(const float* __restrict__ feat,
                                                 const float* __restrict__ bo,
                                                 const float* __restrict__ gamma,
                                                 const float* __restrict__ beta,
                                                 float* __restrict__ out) {
    int row = blockIdx.x;
    int tid = threadIdx.x;  // 512
    int lane = tid & 31, warp = tid >> 5;
    __shared__ float red[16];
    __shared__ float mu_s, rs_s;

    float x = g_tmp[(size_t)row * DM + tid] + bo[tid] + feat[(size_t)row * DM + tid];

    float s = x;
#pragma unroll
    for (int o = 16; o; o >>= 1) s += __shfl_down_sync(0xffffffffu, s, o);
    if (!lane) red[warp] = s;
    __syncthreads();
    if (tid == 0) {
        float t = 0.0f;
#pragma unroll
        for (int i = 0; i < 16; i++) t += red[i];
        mu_s = t * (1.0f / DM);
    }
    __syncthreads();
    float mu = mu_s;
    float d = x - mu;
    float s2 = d * d;
#pragma unroll
    for (int o = 16; o; o >>= 1) s2 += __shfl_down_sync(0xffffffffu, s2, o);
    if (!lane) red[warp] = s2;
    __syncthreads();
    if (tid == 0) {
        float t = 0.0f;
#pragma unroll
        for (int i = 0; i < 16; i++) t += red[i];
        rs_s = rsqrtf(t * (1.0f / DM) + 1e-5f);
    }
    __syncthreads();
    out[(size_t)row * DM + tid] = d * rs_s * gamma[tid] + beta[tid];
}

// ---------------- launch ---------------------------------------------------------
extern "C" void kernel_launch(void* const* d_in, const int* in_sizes, int n_in,
                              void* d_out, int out_size) {
    const float* pos   = (const float*)d_in[0];
    const float* feat  = (const float*)d_in[1];
    const float* Wq    = (const float*)d_in[3];
    const float* Wk    = (const float*)d_in[4];
    const float* Wv    = (const float*)d_in[5];
    const float* Wo    = (const float*)d_in[6];
    const float* bo    = (const float*)d_in[7];
    const float* Wpos  = (const float*)d_in[8];
    const float* bpos  = (const float*)d_in[9];
    const float* temp  = (const float*)d_in[10];
    const float* gamma = (const float*)d_in[11];
    const float* beta  = (const float*)d_in[12];
    float* out = (float*)d_out;

    float *pQ, *pK, *pV, *pAtt, *pTmp;
    cudaGetSymbolAddress((void**)&pQ,   g_Q);
    cudaGetSymbolAddress((void**)&pK,   g_K);
    cudaGetSymbolAddress((void**)&pV,   g_V);
    cudaGetSymbolAddress((void**)&pAtt, g_att);
    cudaGetSymbolAddress((void**)&pTmp, g_tmp);

    knn_kernel<<<ROWS / QW, 256>>>(pos);

    dim3 qkv_grid(DM / BN, ROWS / BM, 3);
    gemm_qkv_kernel<<<qkv_grid, 256>>>(feat, Wq, Wk, Wv, pQ, pK, pV);

    attn_kernel<<<ROWS * NH * 32 / 256, 256>>>(pos, Wpos, bpos, temp);

    dim3 ggrid(DM / BN, ROWS / BM);
    gemm_kernel<<<ggrid, 256>>>(pAtt, Wo, pTmp, ROWS, DM, DM);

    ln_kernel<<<ROWS, 512>>>(feat, bo, gamma, beta, out);
}

// round 6
// speedup vs baseline: 2.9749x; 1.4378x over previous
#include <cuda_runtime.h>
#include <cuda_bf16.h>
#include <math.h>
#include <stdint.h>

#define BATCH 2
#define NPTS 4096
#define DM 512
#define NH 8
#define DH 64
#define KNB 16
#define ROWS (BATCH * NPTS)   // 8192

// ---------------- scratch (device globals; no allocation allowed) ----------------
__device__ float g_Q[ROWS * DM];
__device__ float g_K[ROWS * DM];
__device__ float g_V[ROWS * DM];
__device__ float g_att[ROWS * DM];
__device__ float g_tmp[ROWS * DM];
__device__ int   g_idx[ROWS * KNB];
__device__ __nv_bfloat16 g_Ahi[ROWS * DM];      // activation split (feat, later att)
__device__ __nv_bfloat16 g_Alo[ROWS * DM];
__device__ __nv_bfloat16 g_Bhi[4 * DM * DM];    // transposed weight split [z][n*DM+k]
__device__ __nv_bfloat16 g_Blo[4 * DM * DM];

// ---------------- kNN: warp per query, branch-free sorted top-17 -----------------
#define QW 8
__global__ __launch_bounds__(256) void knn_kernel(const float* __restrict__ pos) {
    __shared__ unsigned long long smrg[QW][32][KNB + 2];
    int warp = threadIdx.x >> 5, lane = threadIdx.x & 31;
    int q = blockIdx.x * QW + warp;
    int b = q >> 12;
    int n = q & (NPTS - 1);
    const float* pb = pos + (size_t)b * NPTS * 3;
    float qx = pb[n * 3 + 0], qy = pb[n * 3 + 1], qz = pb[n * 3 + 2];

    unsigned long long key[KNB + 1];
#pragma unroll
    for (int i = 0; i < KNB + 1; i++) key[i] = 0xFFFFFFFFFFFFFFFFull;

    for (int step = 0; step < NPTS / 32; step++) {
        int j = step * 32 + lane;
        float dx = qx - __ldg(&pb[j * 3 + 0]);
        float dy = qy - __ldg(&pb[j * 3 + 1]);
        float dz = qz - __ldg(&pb[j * 3 + 2]);
        float d = fmaf(dx, dx, fmaf(dy, dy, dz * dz));
        unsigned long long kk =
            ((unsigned long long)__float_as_uint(d) << 32) | (unsigned)j;
        if (kk < key[KNB]) {
#pragma unroll
            for (int p = KNB; p >= 1; p--) {
                unsigned long long lower = key[p - 1];
                unsigned long long cur   = key[p];
                key[p] = (kk >= cur) ? cur : ((kk >= lower) ? kk : lower);
            }
            key[0] = (kk < key[0]) ? kk : key[0];
        }
    }

#pragma unroll
    for (int i = 0; i < KNB + 1; i++) smrg[warp][lane][i] = key[i];
    smrg[warp][lane][KNB + 1] = 0xFFFFFFFFFFFFFFFFull;
    __syncwarp();

    int p = 0;
    unsigned long long head = smrg[warp][lane][0];
    for (int out = 0; out < KNB + 1; out++) {
        unsigned long long m = head;
#pragma unroll
        for (int off = 16; off; off >>= 1) {
            unsigned long long o = __shfl_xor_sync(0xffffffffu, m, off);
            if (o < m) m = o;
        }
        if (out > 0 && lane == 0)
            g_idx[q * KNB + out - 1] = (int)(unsigned)m;
        if (head == m) { p++; head = smrg[warp][lane][p]; }
    }
}

// ---------------- split fp32 -> bf16 hi/lo ---------------------------------------
__global__ __launch_bounds__(256) void split_kernel(const float* __restrict__ src) {
    int i = blockIdx.x * blockDim.x + threadIdx.x;          // float4 index
    float4 v = *(const float4*)&src[i * 4];
    __nv_bfloat16 h0 = __float2bfloat16(v.x), h1 = __float2bfloat16(v.y);
    __nv_bfloat16 h2 = __float2bfloat16(v.z), h3 = __float2bfloat16(v.w);
    __nv_bfloat16 l0 = __float2bfloat16(v.x - __bfloat162float(h0));
    __nv_bfloat16 l1 = __float2bfloat16(v.y - __bfloat162float(h1));
    __nv_bfloat16 l2 = __float2bfloat16(v.z - __bfloat162float(h2));
    __nv_bfloat16 l3 = __float2bfloat16(v.w - __bfloat162float(h3));
    uint2 h, l;
    h.x = ((unsigned)__bfloat16_as_ushort(h1) << 16) | __bfloat16_as_ushort(h0);
    h.y = ((unsigned)__bfloat16_as_ushort(h3) << 16) | __bfloat16_as_ushort(h2);
    l.x = ((unsigned)__bfloat16_as_ushort(l1) << 16) | __bfloat16_as_ushort(l0);
    l.y = ((unsigned)__bfloat16_as_ushort(l3) << 16) | __bfloat16_as_ushort(l2);
    *(uint2*)&g_Ahi[i * 4] = h;
    *(uint2*)&g_Alo[i * 4] = l;
}

// ---------------- weight transpose + split: out[z][n*DM+k] = W_z[k*DM+n] ---------
__global__ __launch_bounds__(256) void transpose_split_kernel(const float* __restrict__ W0,
                                                              const float* __restrict__ W1,
                                                              const float* __restrict__ W2,
                                                              const float* __restrict__ W3) {
    __shared__ float t[32][33];
    const float* src = (blockIdx.z == 0) ? W0 : (blockIdx.z == 1) ? W1
                     : (blockIdx.z == 2) ? W2 : W3;
    size_t zoff = (size_t)blockIdx.z * DM * DM;
    int bx = blockIdx.x * 32, by = blockIdx.y * 32;
    int tx = threadIdx.x & 31, ty = threadIdx.x >> 5;   // 32 x 8
#pragma unroll
    for (int i = 0; i < 32; i += 8)
        t[ty + i][tx] = src[(size_t)(by + ty + i) * DM + bx + tx];
    __syncthreads();
#pragma unroll
    for (int i = 0; i < 32; i += 8) {
        float v = t[tx][ty + i];
        __nv_bfloat16 h = __float2bfloat16(v);
        __nv_bfloat16 l = __float2bfloat16(v - __bfloat162float(h));
        size_t o = zoff + (size_t)(bx + ty + i) * DM + by + tx;
        g_Bhi[o] = h;
        g_Blo[o] = l;
    }
}

// ---------------- HMMA bf16x3 GEMM: C[M,512] = A[M,512] * Bt[512,512]^T ----------
// Tile 128x128, BK=32, cp.async double buffer, ldmatrix, mma.sync m16n8k16.
#define BKC 32
#define NCH (DM / BKC)        // 16
#define ST_A_HI 0
#define ST_A_LO 8192
#define ST_B_HI 16384
#define ST_B_LO 24576
#define STAGE 32768
#define GEMM_SMEM (2 * STAGE)

__device__ __forceinline__ uint32_t smem_u32(const void* p) {
    uint32_t a;
    asm("{ .reg .u64 t; cvta.to.shared.u64 t, %1; cvt.u32.u64 %0, t; }"
        : "=r"(a) : "l"(p));
    return a;
}
#define CP16(dst, src) \
    asm volatile("cp.async.cg.shared.global [%0], [%1], 16;" :: "r"(dst), "l"(src))
#define CP_COMMIT() asm volatile("cp.async.commit_group;" ::: "memory")
#define CP_WAIT(n)  asm volatile("cp.async.wait_group %0;" :: "n"(n) : "memory")

__device__ __forceinline__ void ldmx4(uint32_t* r, uint32_t addr) {
    asm volatile("ldmatrix.sync.aligned.m8n8.x4.shared.b16 {%0,%1,%2,%3}, [%4];"
                 : "=r"(r[0]), "=r"(r[1]), "=r"(r[2]), "=r"(r[3]) : "r"(addr));
}
__device__ __forceinline__ void mma16816(float* c, const uint32_t* a, const uint32_t* b) {
    asm volatile(
        "mma.sync.aligned.m16n8k16.row.col.f32.bf16.bf16.f32 "
        "{%0,%1,%2,%3}, {%4,%5,%6,%7}, {%8,%9}, {%0,%1,%2,%3};"
        : "+f"(c[0]), "+f"(c[1]), "+f"(c[2]), "+f"(c[3])
        : "r"(a[0]), "r"(a[1]), "r"(a[2]), "r"(a[3]), "r"(b[0]), "r"(b[1]));
}

__device__ __forceinline__ void tc_gemm_body(const __nv_bfloat16* __restrict__ Ahi,
                                             const __nv_bfloat16* __restrict__ Alo,
                                             const __nv_bfloat16* __restrict__ Bhi,
                                             const __nv_bfloat16* __restrict__ Blo,
                                             float* __restrict__ C) {
    extern __shared__ __align__(128) char smem[];
    uint32_t sb = smem_u32(smem);
    int tid = threadIdx.x;             // 256
    int wid = tid >> 5, lane = tid & 31;
    int warp_m = wid & 3, warp_n = wid >> 2;       // 4 x 2 warps -> 32x64 warp tile
    int bm = blockIdx.y * 128, bn = blockIdx.x * 128;

    // staging map: thread loads 2x16B per array per chunk
    int r0 = (tid * 2) >> 2, c0 = (tid * 2) & 3;       // chunk 0
    int r1 = (tid * 2 + 1) >> 2, c1 = (tid * 2 + 1) & 3;
    uint32_t d0 = (uint32_t)(r0 * 64 + ((c0 ^ ((r0 >> 1) & 3)) << 4));
    uint32_t d1 = (uint32_t)(r1 * 64 + ((c1 ^ ((r1 >> 1) & 3)) << 4));

    float c[2][8][4];
#pragma unroll
    for (int mt = 0; mt < 2; mt++)
#pragma unroll
        for (int nt = 0; nt < 8; nt++)
#pragma unroll
            for (int e = 0; e < 4; e++) c[mt][nt][e] = 0.0f;

    // per-lane ldmatrix addressing (byte offsets inside a stage)
    int arow = warp_m * 32 + (lane & 15);               // + mt*16
    int akh  = lane >> 4;                               // k-half
    int axor = (arow >> 1) & 3;
    int brow = warp_n * 64 + (lane & 7) + ((lane >> 4) << 3);   // + np*16
    int bkh  = (lane >> 3) & 1;
    int bxor = (brow >> 1) & 3;

    // prologue: load chunk 0
#pragma unroll
    for (int arr = 0; arr < 4; arr++) {
        const __nv_bfloat16* g = (arr == 0) ? Ahi : (arr == 1) ? Alo
                               : (arr == 2) ? Bhi : Blo;
        int rowbase = (arr < 2) ? bm : bn;
        uint32_t dst = sb + arr * 8192;
        CP16(dst + d0, &g[(size_t)(rowbase + r0) * DM + c0 * 8]);
        CP16(dst + d1, &g[(size_t)(rowbase + r1) * DM + c1 * 8]);
    }
    CP_COMMIT();

    for (int kc = 0; kc < NCH; kc++) {
        if (kc + 1 < NCH) {
            uint32_t stg = sb + ((kc + 1) & 1) * STAGE;
            int koff = (kc + 1) * BKC;
#pragma unroll
            for (int arr = 0; arr < 4; arr++) {
                const __nv_bfloat16* g = (arr == 0) ? Ahi : (arr == 1) ? Alo
                                       : (arr == 2) ? Bhi : Blo;
                int rowbase = (arr < 2) ? bm : bn;
                uint32_t dst = stg + arr * 8192;
                CP16(dst + d0, &g[(size_t)(rowbase + r0) * DM + koff + c0 * 8]);
                CP16(dst + d1, &g[(size_t)(rowbase + r1) * DM + koff + c1 * 8]);
            }
            CP_COMMIT();
            CP_WAIT(1);
        } else {
            CP_WAIT(0);
        }
        __syncthreads();

        uint32_t stg = sb + (kc & 1) * STAGE;
#pragma unroll
        for (int ks = 0; ks < 2; ks++) {
            uint32_t ah[2][4], al[2][4];
#pragma unroll
            for (int mt = 0; mt < 2; mt++) {
                uint32_t rbase = stg + (uint32_t)((arow + mt * 16) * 64);
                uint32_t ch = (uint32_t)(((ks * 2 + akh) ^ axor) << 4);
                ldmx4(ah[mt], rbase + ST_A_HI + ch);
                ldmx4(al[mt], rbase + ST_A_LO + ch);
            }
            uint32_t bh[4][4], bl[4][4];
#pragma unroll
            for (int np = 0; np < 4; np++) {
                uint32_t rbase = stg + (uint32_t)((brow + np * 16) * 64);
                uint32_t ch = (uint32_t)(((ks * 2 + bkh) ^ bxor) << 4);
                ldmx4(bh[np], rbase + ST_B_HI + ch);
                ldmx4(bl[np], rbase + ST_B_LO + ch);
            }
#pragma unroll
            for (int mt = 0; mt < 2; mt++)
#pragma unroll
                for (int np = 0; np < 4; np++) {
                    mma16816(c[mt][np * 2 + 0], ah[mt], &bh[np][0]);
                    mma16816(c[mt][np * 2 + 1], ah[mt], &bh[np][2]);
                    mma16816(c[mt][np * 2 + 0], ah[mt], &bl[np][0]);
                    mma16816(c[mt][np * 2 + 1], ah[mt], &bl[np][2]);
                    mma16816(c[mt][np * 2 + 0], al[mt], &bh[np][0]);
                    mma16816(c[mt][np * 2 + 1], al[mt], &bh[np][2]);
                }
        }
        __syncthreads();
    }

    // epilogue
    int gid = lane >> 2, t4 = lane & 3;
#pragma unroll
    for (int mt = 0; mt < 2; mt++) {
        int r = bm + warp_m * 32 + mt * 16 + gid;
#pragma unroll
        for (int nt = 0; nt < 8; nt++) {
            int col = bn + warp_n * 64 + nt * 8 + t4 * 2;
            *(float2*)&C[(size_t)r * DM + col] =
                make_float2(c[mt][nt][0], c[mt][nt][1]);
            *(float2*)&C[(size_t)(r + 8) * DM + col] =
                make_float2(c[mt][nt][2], c[mt][nt][3]);
        }
    }
}

__global__ __launch_bounds__(256, 1) void gemm_qkv_tc(float* __restrict__ Cq,
                                                      float* __restrict__ Ck,
                                                      float* __restrict__ Cv) {
    size_t z = blockIdx.z;
    float* C = (z == 0) ? Cq : (z == 1) ? Ck : Cv;
    tc_gemm_body(g_Ahi, g_Alo, g_Bhi + z * DM * DM, g_Blo + z * DM * DM, C);
}
__global__ __launch_bounds__(256, 1) void gemm_o_tc(float* __restrict__ C) {
    tc_gemm_body(g_Ahi, g_Alo, g_Bhi + (size_t)3 * DM * DM, g_Blo + (size_t)3 * DM * DM, C);
}

// ---------------- attention: warp per (row, head) --------------------------------
__global__ __launch_bounds__(256) void attn_kernel(const float* __restrict__ pos,
                                                   const float* __restrict__ Wpos,
                                                   const float* __restrict__ bpos,
                                                   const float* __restrict__ temp) {
    int gw   = (blockIdx.x * blockDim.x + threadIdx.x) >> 5;
    int lane = threadIdx.x & 31;
    int row  = gw >> 3;
    int h    = gw & 7;
    int b    = row >> 12;
    int n    = row & (NPTS - 1);
    const float* posb = pos + (size_t)b * NPTS * 3;
    int base = (b << 12);

    int j = 0;
    float rx = 0.f, ry = 0.f, rz = 0.f;
    float px = posb[n * 3 + 0], py = posb[n * 3 + 1], pz = posb[n * 3 + 2];
    if (lane < KNB) {
        j  = g_idx[row * KNB + lane];
        rx = px - posb[j * 3 + 0];
        ry = py - posb[j * 3 + 1];
        rz = pz - posb[j * 3 + 2];
    }

    float invT = 1.0f / temp[0];
    float2 q = *(const float2*)&g_Q[(size_t)row * DM + h * DH + 2 * lane];
    q.x *= invT; q.y *= invT;
    float2 w0 = *(const float2*)&Wpos[0 * 128 + 2 * lane];
    float2 w1 = *(const float2*)&Wpos[1 * 128 + 2 * lane];
    float2 w2 = *(const float2*)&Wpos[2 * 128 + 2 * lane];
    float2 bp = *(const float2*)&bpos[2 * lane];

    float myscore = 0.0f;
#pragma unroll
    for (int k = 0; k < KNB; k++) {
        int   jk  = __shfl_sync(0xffffffffu, j,  k);
        float rxk = __shfl_sync(0xffffffffu, rx, k);
        float ryk = __shfl_sync(0xffffffffu, ry, k);
        float rzk = __shfl_sync(0xffffffffu, rz, k);
        float2 kv = *(const float2*)&g_K[(size_t)(base + jk) * DM + h * DH + 2 * lane];
        float pex = fmaf(rxk, w0.x, fmaf(ryk, w1.x, fmaf(rzk, w2.x, bp.x)));
        float pey = fmaf(rxk, w0.y, fmaf(ryk, w1.y, fmaf(rzk, w2.y, bp.y)));
        float s = fmaf(q.x, kv.x + pex, q.y * (kv.y + pey));
#pragma unroll
        for (int off = 16; off; off >>= 1)
            s += __shfl_xor_sync(0xffffffffu, s, off);
        if (lane == k) myscore = s;
    }

    float sc = (lane < KNB) ? myscore : -INFINITY;
    float m = sc;
#pragma unroll
    for (int off = 8; off; off >>= 1)
        m = fmaxf(m, __shfl_xor_sync(0xffffffffu, m, off));
    float e = (lane < KNB) ? __expf(sc - m) : 0.0f;
    float sum = e;
#pragma unroll
    for (int off = 8; off; off >>= 1)
        sum += __shfl_xor_sync(0xffffffffu, sum, off);
    float w = e / sum;

    float2 acc = make_float2(0.f, 0.f);
#pragma unroll
    for (int k = 0; k < KNB; k++) {
        float wk = __shfl_sync(0xffffffffu, w, k);
        int   jk = __shfl_sync(0xffffffffu, j, k);
        float2 v = *(const float2*)&g_V[(size_t)(base + jk) * DM + h * DH + 2 * lane];
        acc.x = fmaf(wk, v.x, acc.x);
        acc.y = fmaf(wk, v.y, acc.y);
    }
    *(float2*)&g_att[(size_t)row * DM + h * DH + 2 * lane] = acc;
}

// ---------------- epilogue: +bo, +residual, LayerNorm ----------------------------
__global__ __launch_bounds__(512) void ln_kernel(const float* __restrict__ feat,
                                                 const float* __restrict__ bo,
                                                 const float* __restrict__ gamma,
                                                 const float* __restrict__ beta,
                                                 float* __restrict__ out) {
    int row = blockIdx.x;
    int tid = threadIdx.x;
    int lane = tid & 31, warp = tid >> 5;
    __shared__ float red[16];
    __shared__ float mu_s, rs_s;

    float x = g_tmp[(size_t)row * DM + tid] + bo[tid] + feat[(size_t)row * DM + tid];

    float s = x;
#pragma unroll
    for (int o = 16; o; o >>= 1) s += __shfl_down_sync(0xffffffffu, s, o);
    if (!lane) red[warp] = s;
    __syncthreads();
    if (tid == 0) {
        float t = 0.0f;
#pragma unroll
        for (int i = 0; i < 16; i++) t += red[i];
        mu_s = t * (1.0f / DM);
    }
    __syncthreads();
    float mu = mu_s;
    float d = x - mu;
    float s2 = d * d;
#pragma unroll
    for (int o = 16; o; o >>= 1) s2 += __shfl_down_sync(0xffffffffu, s2, o);
    if (!lane) red[warp] = s2;
    __syncthreads();
    if (tid == 0) {
        float t = 0.0f;
#pragma unroll
        for (int i = 0; i < 16; i++) t += red[i];
        rs_s = rsqrtf(t * (1.0f / DM) + 1e-5f);
    }
    __syncthreads();
    out[(size_t)row * DM + tid] = d * rs_s * gamma[tid] + beta[tid];
}

// ---------------- launch ---------------------------------------------------------
extern "C" void kernel_launch(void* const* d_in, const int* in_sizes, int n_in,
                              void* d_out, int out_size) {
    const float* pos   = (const float*)d_in[0];
    const float* feat  = (const float*)d_in[1];
    const float* Wq    = (const float*)d_in[3];
    const float* Wk    = (const float*)d_in[4];
    const float* Wv    = (const float*)d_in[5];
    const float* Wo    = (const float*)d_in[6];
    const float* bo    = (const float*)d_in[7];
    const float* Wpos  = (const float*)d_in[8];
    const float* bpos  = (const float*)d_in[9];
    const float* temp  = (const float*)d_in[10];
    const float* gamma = (const float*)d_in[11];
    const float* beta  = (const float*)d_in[12];
    float* out = (float*)d_out;

    float *pQ, *pK, *pV, *pAtt, *pTmp;
    cudaGetSymbolAddress((void**)&pQ,   g_Q);
    cudaGetSymbolAddress((void**)&pK,   g_K);
    cudaGetSymbolAddress((void**)&pV,   g_V);
    cudaGetSymbolAddress((void**)&pAtt, g_att);
    cudaGetSymbolAddress((void**)&pTmp, g_tmp);

    cudaFuncSetAttribute(gemm_qkv_tc, cudaFuncAttributeMaxDynamicSharedMemorySize, GEMM_SMEM);
    cudaFuncSetAttribute(gemm_o_tc,   cudaFuncAttributeMaxDynamicSharedMemorySize, GEMM_SMEM);

    knn_kernel<<<ROWS / QW, 256>>>(pos);

    split_kernel<<<ROWS * DM / 4 / 256, 256>>>(feat);
    transpose_split_kernel<<<dim3(DM / 32, DM / 32, 4), 256>>>(Wq, Wk, Wv, Wo);

    gemm_qkv_tc<<<dim3(DM / 128, ROWS / 128, 3), 256, GEMM_SMEM>>>(pQ, pK, pV);

    attn_kernel<<<ROWS * NH * 32 / 256, 256>>>(pos, Wpos, bpos, temp);

    split_kernel<<<ROWS * DM / 4 / 256, 256>>>(pAtt);
    gemm_o_tc<<<dim3(DM / 128, ROWS / 128), 256, GEMM_SMEM>>>(pTmp);

    ln_kernel<<<ROWS, 512>>>(feat, bo, gamma, beta, out);
}

// round 7
// speedup vs baseline: 3.3744x; 1.1343x over previous
#include <cuda_runtime.h>
#include <cuda_bf16.h>
#include <math.h>
#include <stdint.h>

#define BATCH 2
#define NPTS 4096
#define DM 512
#define NH 8
#define DH 64
#define KNB 16
#define ROWS (BATCH * NPTS)   // 8192

// ---------------- scratch (device globals; no allocation allowed) ----------------
__device__ float g_Q[ROWS * DM];
__device__ float g_K[ROWS * DM];
__device__ float g_V[ROWS * DM];
__device__ float g_tmp[ROWS * DM];
__device__ int   g_idx[ROWS * KNB];
__device__ __nv_bfloat16 g_Ahi[ROWS * DM];      // activation split (feat, later att)
__device__ __nv_bfloat16 g_Alo[ROWS * DM];
__device__ __nv_bfloat16 g_Bhi[4 * DM * DM];    // transposed weight split [z][n*DM+k]
__device__ __nv_bfloat16 g_Blo[4 * DM * DM];

// ---------------- helpers --------------------------------------------------------
__device__ __forceinline__ uint32_t smem_u32(const void* p) {
    uint32_t a;
    asm("{ .reg .u64 t; cvta.to.shared.u64 t, %1; cvt.u32.u64 %0, t; }"
        : "=r"(a) : "l"(p));
    return a;
}
#define CP16(dst, src) \
    asm volatile("cp.async.cg.shared.global [%0], [%1], 16;" :: "r"(dst), "l"(src))
#define CP_COMMIT() asm volatile("cp.async.commit_group;" ::: "memory")
#define CP_WAIT(n)  asm volatile("cp.async.wait_group %0;" :: "n"(n) : "memory")

__device__ __forceinline__ void ldmx4(uint32_t* r, uint32_t addr) {
    asm volatile("ldmatrix.sync.aligned.m8n8.x4.shared.b16 {%0,%1,%2,%3}, [%4];"
                 : "=r"(r[0]), "=r"(r[1]), "=r"(r[2]), "=r"(r[3]) : "r"(addr));
}
__device__ __forceinline__ void mma16816(float* c, const uint32_t* a, const uint32_t* b) {
    asm volatile(
        "mma.sync.aligned.m16n8k16.row.col.f32.bf16.bf16.f32 "
        "{%0,%1,%2,%3}, {%4,%5,%6,%7}, {%8,%9}, {%0,%1,%2,%3};"
        : "+f"(c[0]), "+f"(c[1]), "+f"(c[2]), "+f"(c[3])
        : "r"(a[0]), "r"(a[1]), "r"(a[2]), "r"(a[3]), "r"(b[0]), "r"(b[1]));
}

// ---------------- prep: split feat + transpose/split weights (fused grid) --------
__global__ __launch_bounds__(256) void prep_kernel(const float* __restrict__ feat,
                                                   const float* __restrict__ W0,
                                                   const float* __restrict__ W1,
                                                   const float* __restrict__ W2,
                                                   const float* __restrict__ W3) {
    __shared__ float t[32][33];
    if (blockIdx.x < 4096) {                      // split feat: 4096 CTAs
        int i = blockIdx.x * blockDim.x + threadIdx.x;
        float4 v = *(const float4*)&feat[(size_t)i * 4];
        __nv_bfloat16 h0 = __float2bfloat16(v.x), h1 = __float2bfloat16(v.y);
        __nv_bfloat16 h2 = __float2bfloat16(v.z), h3 = __float2bfloat16(v.w);
        __nv_bfloat16 l0 = __float2bfloat16(v.x - __bfloat162float(h0));
        __nv_bfloat16 l1 = __float2bfloat16(v.y - __bfloat162float(h1));
        __nv_bfloat16 l2 = __float2bfloat16(v.z - __bfloat162float(h2));
        __nv_bfloat16 l3 = __float2bfloat16(v.w - __bfloat162float(h3));
        uint2 h, l;
        h.x = ((unsigned)__bfloat16_as_ushort(h1) << 16) | __bfloat16_as_ushort(h0);
        h.y = ((unsigned)__bfloat16_as_ushort(h3) << 16) | __bfloat16_as_ushort(h2);
        l.x = ((unsigned)__bfloat16_as_ushort(l1) << 16) | __bfloat16_as_ushort(l0);
        l.y = ((unsigned)__bfloat16_as_ushort(l3) << 16) | __bfloat16_as_ushort(l2);
        *(uint2*)&g_Ahi[(size_t)i * 4] = h;
        *(uint2*)&g_Alo[(size_t)i * 4] = l;
    } else {                                      // transpose+split: 1024 CTAs
        int id = blockIdx.x - 4096;               // 16 x 16 x 4
        int z = id >> 8;
        int by = ((id >> 4) & 15) * 32, bx = (id & 15) * 32;
        const float* src = (z == 0) ? W0 : (z == 1) ? W1 : (z == 2) ? W2 : W3;
        size_t zoff = (size_t)z * DM * DM;
        int tx = threadIdx.x & 31, ty = threadIdx.x >> 5;   // 32 x 8
#pragma unroll
        for (int i = 0; i < 32; i += 8)
            t[ty + i][tx] = src[(size_t)(by + ty + i) * DM + bx + tx];
        __syncthreads();
#pragma unroll
        for (int i = 0; i < 32; i += 8) {
            float v = t[tx][ty + i];
            __nv_bfloat16 h = __float2bfloat16(v);
            __nv_bfloat16 l = __float2bfloat16(v - __bfloat162float(h));
            size_t o = zoff + (size_t)(bx + ty + i) * DM + by + tx;
            g_Bhi[o] = h;
            g_Blo[o] = l;
        }
    }
}

// ---------------- HMMA bf16x3 GEMM body (reduced register pressure) --------------
#define BKC 32
#define NCH (DM / BKC)        // 16
#define ST_A_HI 0
#define ST_A_LO 8192
#define ST_B_HI 16384
#define ST_B_LO 24576
#define STAGE 32768
#define GEMM_SMEM (2 * STAGE)

__device__ __forceinline__ void tc_gemm_body(char* smem,
                                             const __nv_bfloat16* __restrict__ Ahi,
                                             const __nv_bfloat16* __restrict__ Alo,
                                             const __nv_bfloat16* __restrict__ Bhi,
                                             const __nv_bfloat16* __restrict__ Blo,
                                             float* __restrict__ C,
                                             int bm, int bn) {
    uint32_t sb = smem_u32(smem);
    int tid = threadIdx.x;             // 256
    int wid = tid >> 5, lane = tid & 31;
    int warp_m = wid & 3, warp_n = wid >> 2;       // 4 x 2 warps -> 32x64 warp tile

    int r0 = (tid * 2) >> 2, c0 = (tid * 2) & 3;
    int r1 = (tid * 2 + 1) >> 2, c1 = (tid * 2 + 1) & 3;
    uint32_t d0 = (uint32_t)(r0 * 64 + ((c0 ^ ((r0 >> 1) & 3)) << 4));
    uint32_t d1 = (uint32_t)(r1 * 64 + ((c1 ^ ((r1 >> 1) & 3)) << 4));

    float c[2][8][4];
#pragma unroll
    for (int mt = 0; mt < 2; mt++)
#pragma unroll
        for (int nt = 0; nt < 8; nt++)
#pragma unroll
            for (int e = 0; e < 4; e++) c[mt][nt][e] = 0.0f;

    int arow = warp_m * 32 + (lane & 15);
    int akh  = lane >> 4;
    int axor = (arow >> 1) & 3;
    int brow = warp_n * 64 + (lane & 7) + ((lane >> 4) << 3);
    int bkh  = (lane >> 3) & 1;
    int bxor = (brow >> 1) & 3;

#pragma unroll
    for (int arr = 0; arr < 4; arr++) {
        const __nv_bfloat16* g = (arr == 0) ? Ahi : (arr == 1) ? Alo
                               : (arr == 2) ? Bhi : Blo;
        int rowbase = (arr < 2) ? bm : bn;
        uint32_t dst = sb + arr * 8192;
        CP16(dst + d0, &g[(size_t)(rowbase + r0) * DM + c0 * 8]);
        CP16(dst + d1, &g[(size_t)(rowbase + r1) * DM + c1 * 8]);
    }
    CP_COMMIT();

    for (int kc = 0; kc < NCH; kc++) {
        if (kc + 1 < NCH) {
            uint32_t stg = sb + ((kc + 1) & 1) * STAGE;
            int koff = (kc + 1) * BKC;
#pragma unroll
            for (int arr = 0; arr < 4; arr++) {
                const __nv_bfloat16* g = (arr == 0) ? Ahi : (arr == 1) ? Alo
                                       : (arr == 2) ? Bhi : Blo;
                int rowbase = (arr < 2) ? bm : bn;
                uint32_t dst = stg + arr * 8192;
                CP16(dst + d0, &g[(size_t)(rowbase + r0) * DM + koff + c0 * 8]);
                CP16(dst + d1, &g[(size_t)(rowbase + r1) * DM + koff + c1 * 8]);
            }
            CP_COMMIT();
            CP_WAIT(1);
        } else {
            CP_WAIT(0);
        }
        __syncthreads();

        uint32_t stg = sb + (kc & 1) * STAGE;
#pragma unroll
        for (int ks = 0; ks < 2; ks++) {
            uint32_t ah[2][4], al[2][4];
#pragma unroll
            for (int mt = 0; mt < 2; mt++) {
                uint32_t rbase = stg + (uint32_t)((arow + mt * 16) * 64);
                uint32_t ch = (uint32_t)(((ks * 2 + akh) ^ axor) << 4);
                ldmx4(ah[mt], rbase + ST_A_HI + ch);
                ldmx4(al[mt], rbase + ST_A_LO + ch);
            }
            // B fragments loaded on demand: only 8 operand regs live at a time
#pragma unroll
            for (int np = 0; np < 4; np++) {
                uint32_t rbase = stg + (uint32_t)((brow + np * 16) * 64);
                uint32_t ch = (uint32_t)(((ks * 2 + bkh) ^ bxor) << 4);
                uint32_t bh[4], bl[4];
                ldmx4(bh, rbase + ST_B_HI + ch);
                ldmx4(bl, rbase + ST_B_LO + ch);
#pragma unroll
                for (int mt = 0; mt < 2; mt++) {
                    mma16816(c[mt][np * 2 + 0], ah[mt], &bh[0]);
                    mma16816(c[mt][np * 2 + 1], ah[mt], &bh[2]);
                    mma16816(c[mt][np * 2 + 0], ah[mt], &bl[0]);
                    mma16816(c[mt][np * 2 + 1], ah[mt], &bl[2]);
                    mma16816(c[mt][np * 2 + 0], al[mt], &bh[0]);
                    mma16816(c[mt][np * 2 + 1], al[mt], &bh[2]);
                }
            }
        }
        __syncthreads();
    }

    int gid = lane >> 2, t4 = lane & 3;
#pragma unroll
    for (int mt = 0; mt < 2; mt++) {
        int r = bm + warp_m * 32 + mt * 16 + gid;
#pragma unroll
        for (int nt = 0; nt < 8; nt++) {
            int col = bn + warp_n * 64 + nt * 8 + t4 * 2;
            *(float2*)&C[(size_t)r * DM + col] =
                make_float2(c[mt][nt][0], c[mt][nt][1]);
            *(float2*)&C[(size_t)(r + 8) * DM + col] =
                make_float2(c[mt][nt][2], c[mt][nt][3]);
        }
    }
}

// ---------------- fused: QKV GEMMs + kNN, interleaved CTA groups -----------------
// grid.x = 1792: per 7-group -> 3 gemm CTAs (768 total) + 4 knn CTAs (1024 total)
#define QW 8
__global__ __launch_bounds__(256, 2) void fused_qkv_knn(const float* __restrict__ pos,
                                                        float* __restrict__ Cq,
                                                        float* __restrict__ Ck,
                                                        float* __restrict__ Cv) {
    extern __shared__ __align__(128) char smem[];
    int g7 = blockIdx.x / 7, r7 = blockIdx.x % 7;

    if (r7 < 3) {
        // ---- GEMM CTA ----
        int id = g7 * 3 + r7;              // 0..767
        int z  = id >> 8;                  // 0..2
        int rem = id & 255;
        int bm = (rem >> 2) * 128, bn = (rem & 3) * 128;
        float* C = (z == 0) ? Cq : (z == 1) ? Ck : Cv;
        tc_gemm_body(smem, g_Ahi, g_Alo,
                     g_Bhi + (size_t)z * DM * DM, g_Blo + (size_t)z * DM * DM,
                     C, bm, bn);
    } else {
        // ---- kNN CTA ----
        unsigned long long (*smrg)[32][KNB + 2] =
            (unsigned long long (*)[32][KNB + 2])smem;
        int warp = threadIdx.x >> 5, lane = threadIdx.x & 31;
        int q = (g7 * 4 + (r7 - 3)) * QW + warp;    // 0..8191
        int b = q >> 12;
        int n = q & (NPTS - 1);
        const float* pb = pos + (size_t)b * NPTS * 3;
        float qx = pb[n * 3 + 0], qy = pb[n * 3 + 1], qz = pb[n * 3 + 2];

        unsigned long long key[KNB + 1];
#pragma unroll
        for (int i = 0; i < KNB + 1; i++) key[i] = 0xFFFFFFFFFFFFFFFFull;

        for (int step = 0; step < NPTS / 32; step++) {
            int j = step * 32 + lane;
            float dx = qx - __ldg(&pb[j * 3 + 0]);
            float dy = qy - __ldg(&pb[j * 3 + 1]);
            float dz = qz - __ldg(&pb[j * 3 + 2]);
            float d = fmaf(dx, dx, fmaf(dy, dy, dz * dz));
            unsigned long long kk =
                ((unsigned long long)__float_as_uint(d) << 32) | (unsigned)j;
            if (kk < key[KNB]) {
#pragma unroll
                for (int p = KNB; p >= 1; p--) {
                    unsigned long long lower = key[p - 1];
                    unsigned long long cur   = key[p];
                    key[p] = (kk >= cur) ? cur : ((kk >= lower) ? kk : lower);
                }
                key[0] = (kk < key[0]) ? kk : key[0];
            }
        }

#pragma unroll
        for (int i = 0; i < KNB + 1; i++) smrg[warp][lane][i] = key[i];
        smrg[warp][lane][KNB + 1] = 0xFFFFFFFFFFFFFFFFull;
        __syncwarp();

        int p = 0;
        unsigned long long head = smrg[warp][lane][0];
        for (int out = 0; out < KNB + 1; out++) {
            unsigned long long m = head;
#pragma unroll
            for (int off = 16; off; off >>= 1) {
                unsigned long long o = __shfl_xor_sync(0xffffffffu, m, off);
                if (o < m) m = o;
            }
            if (out > 0 && lane == 0)
                g_idx[q * KNB + out - 1] = (int)(unsigned)m;
            if (head == m) { p++; head = smrg[warp][lane][p]; }
        }
    }
}

__global__ __launch_bounds__(256, 2) void gemm_o_tc(float* __restrict__ C) {
    extern __shared__ __align__(128) char smem[];
    tc_gemm_body(smem, g_Ahi, g_Alo,
                 g_Bhi + (size_t)3 * DM * DM, g_Blo + (size_t)3 * DM * DM,
                 C, blockIdx.y * 128, blockIdx.x * 128);
}

// ---------------- attention: warp per (row, head); writes bf16 hi/lo splits -----
__global__ __launch_bounds__(256) void attn_kernel(const float* __restrict__ pos,
                                                   const float* __restrict__ Wpos,
                                                   const float* __restrict__ bpos,
                                                   const float* __restrict__ temp) {
    int gw   = (blockIdx.x * blockDim.x + threadIdx.x) >> 5;
    int lane = threadIdx.x & 31;
    int row  = gw >> 3;
    int h    = gw & 7;
    int b    = row >> 12;
    int n    = row & (NPTS - 1);
    const float* posb = pos + (size_t)b * NPTS * 3;
    int base = (b << 12);

    int j = 0;
    float rx = 0.f, ry = 0.f, rz = 0.f;
    float px = posb[n * 3 + 0], py = posb[n * 3 + 1], pz = posb[n * 3 + 2];
    if (lane < KNB) {
        j  = g_idx[row * KNB + lane];
        rx = px - posb[j * 3 + 0];
        ry = py - posb[j * 3 + 1];
        rz = pz - posb[j * 3 + 2];
    }

    float invT = 1.0f / temp[0];
    float2 q = *(const float2*)&g_Q[(size_t)row * DM + h * DH + 2 * lane];
    q.x *= invT; q.y *= invT;
    float2 w0 = *(const float2*)&Wpos[0 * 128 + 2 * lane];
    float2 w1 = *(const float2*)&Wpos[1 * 128 + 2 * lane];
    float2 w2 = *(const float2*)&Wpos[2 * 128 + 2 * lane];
    float2 bp = *(const float2*)&bpos[2 * lane];

    float myscore = 0.0f;
#pragma unroll
    for (int k = 0; k < KNB; k++) {
        int   jk  = __shfl_sync(0xffffffffu, j,  k);
        float rxk = __shfl_sync(0xffffffffu, rx, k);
        float ryk = __shfl_sync(0xffffffffu, ry, k);
        float rzk = __shfl_sync(0xffffffffu, rz, k);
        float2 kv = *(const float2*)&g_K[(size_t)(base + jk) * DM + h * DH + 2 * lane];
        float pex = fmaf(rxk, w0.x, fmaf(ryk, w1.x, fmaf(rzk, w2.x, bp.x)));
        float pey = fmaf(rxk, w0.y, fmaf(ryk, w1.y, fmaf(rzk, w2.y, bp.y)));
        float s = fmaf(q.x, kv.x + pex, q.y * (kv.y + pey));
#pragma unroll
        for (int off = 16; off; off >>= 1)
            s += __shfl_xor_sync(0xffffffffu, s, off);
        if (lane == k) myscore = s;
    }

    float sc = (lane < KNB) ? myscore : -INFINITY;
    float m = sc;
#pragma unroll
    for (int off = 8; off; off >>= 1)
        m = fmaxf(m, __shfl_xor_sync(0xffffffffu, m, off));
    float e = (lane < KNB) ? __expf(sc - m) : 0.0f;
    float sum = e;
#pragma unroll
    for (int off = 8; off; off >>= 1)
        sum += __shfl_xor_sync(0xffffffffu, sum, off);
    float w = e / sum;

    float2 acc = make_float2(0.f, 0.f);
#pragma unroll
    for (int k = 0; k < KNB; k++) {
        float wk = __shfl_sync(0xffffffffu, w, k);
        int   jk = __shfl_sync(0xffffffffu, j, k);
        float2 v = *(const float2*)&g_V[(size_t)(base + jk) * DM + h * DH + 2 * lane];
        acc.x = fmaf(wk, v.x, acc.x);
        acc.y = fmaf(wk, v.y, acc.y);
    }
    // write bf16 hi/lo split directly (feeds gemm_o)
    size_t off = (size_t)row * DM + h * DH + 2 * lane;
    __nv_bfloat16 h0 = __float2bfloat16(acc.x);
    __nv_bfloat16 h1 = __float2bfloat16(acc.y);
    __nv_bfloat16 l0 = __float2bfloat16(acc.x - __bfloat162float(h0));
    __nv_bfloat16 l1 = __float2bfloat16(acc.y - __bfloat162float(h1));
    *(uint32_t*)&g_Ahi[off] =
        ((unsigned)__bfloat16_as_ushort(h1) << 16) | __bfloat16_as_ushort(h0);
    *(uint32_t*)&g_Alo[off] =
        ((unsigned)__bfloat16_as_ushort(l1) << 16) | __bfloat16_as_ushort(l0);
}

// ---------------- epilogue: +bo, +residual, LayerNorm ----------------------------
__global__ __launch_bounds__(512) void ln_kernel(const float* __restrict__ feat,
                                                 const float* __restrict__ bo,
                                                 const float* __restrict__ gamma,
                                                 const float* __restrict__ beta,
                                                 float* __restrict__ out) {
    int row = blockIdx.x;
    int tid = threadIdx.x;
    int lane = tid & 31, warp = tid >> 5;
    __shared__ float red[16];
    __shared__ float mu_s, rs_s;

    float x = g_tmp[(size_t)row * DM + tid] + bo[tid] + feat[(size_t)row * DM + tid];

    float s = x;
#pragma unroll
    for (int o = 16; o; o >>= 1) s += __shfl_down_sync(0xffffffffu, s, o);
    if (!lane) red[warp] = s;
    __syncthreads();
    if (tid == 0) {
        float t = 0.0f;
#pragma unroll
        for (int i = 0; i < 16; i++) t += red[i];
        mu_s = t * (1.0f / DM);
    }
    __syncthreads();
    float mu = mu_s;
    float d = x - mu;
    float s2 = d * d;
#pragma unroll
    for (int o = 16; o; o >>= 1) s2 += __shfl_down_sync(0xffffffffu, s2, o);
    if (!lane) red[warp] = s2;
    __syncthreads();
    if (tid == 0) {
        float t = 0.0f;
#pragma unroll
        for (int i = 0; i < 16; i++) t += red[i];
        rs_s = rsqrtf(t * (1.0f / DM) + 1e-5f);
    }
    __syncthreads();
    out[(size_t)row * DM + tid] = d * rs_s * gamma[tid] + beta[tid];
}

// ---------------- launch ---------------------------------------------------------
extern "C" void kernel_launch(void* const* d_in, const int* in_sizes, int n_in,
                              void* d_out, int out_size) {
    const float* pos   = (const float*)d_in[0];
    const float* feat  = (const float*)d_in[1];
    const float* Wq    = (const float*)d_in[3];
    const float* Wk    = (const float*)d_in[4];
    const float* Wv    = (const float*)d_in[5];
    const float* Wo    = (const float*)d_in[6];
    const float* bo    = (const float*)d_in[7];
    const float* Wpos  = (const float*)d_in[8];
    const float* bpos  = (const float*)d_in[9];
    const float* temp  = (const float*)d_in[10];
    const float* gamma = (const float*)d_in[11];
    const float* beta  = (const float*)d_in[12];
    float* out = (float*)d_out;

    float *pQ, *pK, *pV, *pTmp;
    cudaGetSymbolAddress((void**)&pQ,   g_Q);
    cudaGetSymbolAddress((void**)&pK,   g_K);
    cudaGetSymbolAddress((void**)&pV,   g_V);
    cudaGetSymbolAddress((void**)&pTmp, g_tmp);

    cudaFuncSetAttribute(fused_qkv_knn, cudaFuncAttributeMaxDynamicSharedMemorySize, GEMM_SMEM);
    cudaFuncSetAttribute(gemm_o_tc,     cudaFuncAttributeMaxDynamicSharedMemorySize, GEMM_SMEM);

    prep_kernel<<<4096 + 1024, 256>>>(feat, Wq, Wk, Wv, Wo);

    fused_qkv_knn<<<1792, 256, GEMM_SMEM>>>(pos, pQ, pK, pV);

    attn_kernel<<<ROWS * NH * 32 / 256, 256>>>(pos, Wpos, bpos, temp);

    gemm_o_tc<<<dim3(DM / 128, ROWS / 128), 256, GEMM_SMEM>>>(pTmp);

    ln_kernel<<<ROWS, 512>>>(feat, bo, gamma, beta, out);
}